// round 14
// baseline (speedup 1.0000x reference)
#include <cuda_runtime.h>
#include <cuda_fp16.h>
#include <mma.h>
#include <math.h>

using namespace nvcuda;

#define N_NODES 20000
#define N_EDGES 320000
#define TOT_EDGES (N_EDGES + N_NODES)
#define NB_SCAN 79
#define NB_GEMM 313  // ceil(20000/64)

// ---------------- scratch ----------------
__device__ float  g_hA[N_NODES * 64];
__device__ float  g_hB[N_NODES * 64];
__device__ __half g_hproj[N_NODES * 256];
__device__ __half g_Wh[3][64 * 256];
__device__ float  g_asrc[N_NODES * 4];
__device__ float  g_adst[N_NODES * 4];
__device__ int    g_deg[N_NODES + 160];  // + scan lookback state (memset together)
__device__ int    g_off[N_NODES + 1];
__device__ int    g_cursor[N_NODES];
__device__ int    g_srcs[TOT_EDGES];

__device__ __forceinline__ float eluf(float x) { return x > 0.f ? x : (__expf(x) - 1.f); }
__device__ __forceinline__ float lrelu(float x) { return x > 0.f ? x : 0.2f * x; }

__device__ __forceinline__ unsigned long long pack2(float a, float b) {
    unsigned long long r;
    asm("mov.b64 %0,{%1,%2};" : "=l"(r) : "f"(a), "f"(b));
    return r;
}
__device__ __forceinline__ float2 unpk2(unsigned long long v) {
    float2 r;
    asm("mov.b64 {%0,%1},%2;" : "=f"(r.x), "=f"(r.y) : "l"(v));
    return r;
}
__device__ __forceinline__ void fma2(unsigned long long& d, unsigned long long a, unsigned long long b) {
    asm("fma.rn.f32x2 %0,%1,%2,%0;" : "+l"(d) : "l"(a), "l"(b));
}
__device__ __forceinline__ void st_rel64(unsigned long long* p, unsigned long long v) {
    asm volatile("st.release.gpu.global.u64 [%0],%1;" :: "l"(p), "l"(v) : "memory");
}
__device__ __forceinline__ unsigned long long ld_acq64(const unsigned long long* p) {
    unsigned long long v;
    asm volatile("ld.acquire.gpu.global.u64 %0,[%1];" : "=l"(v) : "l"(p));
    return v;
}

__device__ __forceinline__ int detect_is64(const void* ei) {
    const int* w = (const int*)ei;
    int found = 0;
    for (int j = 1 + 2 * threadIdx.x; j < 2048; j += 2 * blockDim.x)
        if (w[j] != 0) found = 1;
    return __syncthreads_or(found) ? 0 : 1;
}

// ---------------- CSR ----------------
__global__ void k_count(const void* ei) {
    int is64 = detect_is64(ei);
    int e = blockIdx.x * blockDim.x + threadIdx.x;
    if (e >= N_EDGES) return;
    int d = is64 ? (int)((const long long*)ei)[N_EDGES + e] : ((const int*)ei)[N_EDGES + e];
    atomicAdd(&g_deg[d], 1);
}

__global__ void k_scan() {
    __shared__ int swsum[8];
    __shared__ int s_prefix;
    unsigned long long* scanpk = (unsigned long long*)&g_deg[N_NODES];
    int tid = threadIdx.x, bid = blockIdx.x;
    int i = bid * 256 + tid;
    int v = (i < N_NODES) ? (g_deg[i] + 1) : 0;
    int lane = tid & 31, w = tid >> 5;
    int s = v;
#pragma unroll
    for (int o = 1; o < 32; o <<= 1) {
        int u = __shfl_up_sync(0xffffffffu, s, o);
        if (lane >= o) s += u;
    }
    if (lane == 31) swsum[w] = s;
    __syncthreads();
    if (w == 0 && lane < 8) {
        int xv = swsum[lane];
#pragma unroll
        for (int o = 1; o < 8; o <<= 1) {
            int u = __shfl_up_sync(0xffu, xv, o);
            if (lane >= o) xv += u;
        }
        swsum[lane] = xv;
    }
    __syncthreads();
    int base = (w > 0) ? swsum[w - 1] : 0;
    int total = swsum[7];
    if (tid == 0) {
        int prefix = 0;
        if (bid == 0) {
            st_rel64(&scanpk[0], (2ull << 32) | (unsigned)total);
        } else {
            st_rel64(&scanpk[bid], (1ull << 32) | (unsigned)total);
            int i2 = bid - 1;
            while (i2 >= 0) {
                unsigned long long pk = ld_acq64(&scanpk[i2]);
                unsigned f = (unsigned)(pk >> 32);
                if (f == 0) { __nanosleep(30); continue; }
                prefix += (int)(unsigned)pk;
                if (f == 2u) break;
                i2--;
            }
            st_rel64(&scanpk[bid], (2ull << 32) | (unsigned)(prefix + total));
        }
        s_prefix = prefix;
        if (bid == 0) g_off[N_NODES] = TOT_EDGES;
    }
    __syncthreads();
    if (i < N_NODES) {
        int off = s_prefix + base + s - v;
        g_off[i] = off;
        g_cursor[i] = off;
    }
}

__global__ void k_scatter(const void* ei) {
    int is64 = detect_is64(ei);
    int e = blockIdx.x * blockDim.x + threadIdx.x;
    if (e >= TOT_EDGES) return;
    int s, d;
    if (e < N_EDGES) {
        if (is64) {
            s = (int)((const long long*)ei)[e];
            d = (int)((const long long*)ei)[N_EDGES + e];
        } else {
            s = ((const int*)ei)[e];
            d = ((const int*)ei)[N_EDGES + e];
        }
    } else {
        s = d = e - N_EDGES;
    }
    int p = atomicAdd(&g_cursor[d], 1);
    g_srcs[p] = s;
}

// ---------------- W -> fp16 conversion (once per call) ----------------
__global__ void k_wconv(const float* __restrict__ W1, const float* __restrict__ W2,
                        const float* __restrict__ W3) {
    int i = blockIdx.x * 256 + threadIdx.x;
    if (i < 16384) {
        g_Wh[0][i] = __float2half(W1[i]);
        g_Wh[1][i] = __float2half(W2[i]);
        g_Wh[2][i] = __float2half(W3[i]);
    }
}

// =======================================================================
// Tensor-core projection GEMM: [64 rows x 256 cols], k=64.
// 8 warps: rowg = w&1 (32 rows), colg = w>>1 (64 cols). fp32 accumulate.
// Epilogue: 2 passes of 128 cols through fp32 staging -> hproj fp16 + att dots.
// smem layout (bytes):
//   Ws   half [64][256]   @ 0      (32768)
//   Xs   half [64][64]    @ 32768  (8192)
//   stag float[64][128]   @ 40960  (32768)
//   sAs  float[256]       @ 73728  (1024)
//   sAd  float[256]       @ 74752  (1024)   -> 75776  (att kernel)
//   enc: sE1 @75776(1024) sB1 @76800(128) sE2 @76928(8192) sB2 @85120(256) -> 85376
// =======================================================================
#define SM_WS 0
#define SM_XS 32768
#define SM_STAG 40960
#define SM_AS 73728
#define SM_AD 74752
#define SMEM_ATT 75776
#define SM_E1 75776
#define SM_B1 76800
#define SM_E2 76928
#define SM_B2 85120
#define SMEM_ENC 85376

__device__ __forceinline__ void gemm_tc_core(char* smem, int row0) {
    __half* Ws = (__half*)(smem + SM_WS);
    __half* Xs = (__half*)(smem + SM_XS);
    float* stag = (float*)(smem + SM_STAG);
    float* sAs = (float*)(smem + SM_AS);
    float* sAd = (float*)(smem + SM_AD);
    int tid = threadIdx.x;
    int wid = tid >> 5, lane = tid & 31;
    int rowg = wid & 1, colg = wid >> 1;

    wmma::fragment<wmma::accumulator, 16, 16, 16, float> cf[2][4];
#pragma unroll
    for (int mi = 0; mi < 2; mi++)
#pragma unroll
        for (int ni = 0; ni < 4; ni++) wmma::fill_fragment(cf[mi][ni], 0.f);

#pragma unroll
    for (int ks = 0; ks < 4; ks++) {
        wmma::fragment<wmma::matrix_a, 16, 16, 16, __half, wmma::row_major> af[2];
#pragma unroll
        for (int mi = 0; mi < 2; mi++)
            wmma::load_matrix_sync(af[mi], Xs + (rowg * 32 + mi * 16) * 64 + ks * 16, 64);
#pragma unroll
        for (int ni = 0; ni < 4; ni++) {
            wmma::fragment<wmma::matrix_b, 16, 16, 16, __half, wmma::row_major> bf;
            wmma::load_matrix_sync(bf, Ws + ks * 16 * 256 + colg * 64 + ni * 16, 256);
#pragma unroll
            for (int mi = 0; mi < 2; mi++)
                wmma::mma_sync(cf[mi][ni], af[mi], bf, cf[mi][ni]);
        }
    }

    int headL = lane >> 4;
    int cpos = (lane & 15) * 4;
#pragma unroll
    for (int pass = 0; pass < 2; pass++) {
        if ((wid >> 2) == pass) {
#pragma unroll
            for (int mi = 0; mi < 2; mi++)
#pragma unroll
                for (int ni = 0; ni < 4; ni++)
                    wmma::store_matrix_sync(
                        stag + (rowg * 32 + mi * 16) * 128 + (colg & 1) * 64 + ni * 16,
                        cf[mi][ni], 128, wmma::mem_row_major);
        }
        __syncthreads();
        // staging -> fp16 hproj
#pragma unroll
        for (int j = 0; j < 8; j++) {
            int idx = j * 1024 + tid * 4;
            int row = idx >> 7, col = idx & 127;
            int n = row0 + row;
            if (n < N_NODES) {
                float4 v = *(float4*)&stag[row * 128 + col];
                __half2 h0 = __floats2half2_rn(v.x, v.y);
                __half2 h1 = __floats2half2_rn(v.z, v.w);
                uint2 st;
                st.x = *(unsigned*)&h0;
                st.y = *(unsigned*)&h1;
                *(uint2*)&g_hproj[(long long)n * 256 + pass * 128 + col] = st;
            }
        }
        // att dots from fp32 staging (2 heads per pass)
        int hg = pass * 2 + headL;
        float4 a4 = *(float4*)&sAs[hg * 64 + cpos];
        float4 d4 = *(float4*)&sAd[hg * 64 + cpos];
#pragma unroll
        for (int rr = 0; rr < 8; rr++) {
            int row = wid * 8 + rr;
            float4 h4 = *(float4*)&stag[row * 128 + headL * 64 + cpos];
            float ps = h4.x * a4.x + h4.y * a4.y + h4.z * a4.z + h4.w * a4.w;
            float pd = h4.x * d4.x + h4.y * d4.y + h4.z * d4.z + h4.w * d4.w;
#pragma unroll
            for (int o = 8; o >= 1; o >>= 1) {
                ps += __shfl_down_sync(0xffffffffu, ps, o, 16);
                pd += __shfl_down_sync(0xffffffffu, pd, o, 16);
            }
            int n = row0 + row;
            if ((lane & 15) == 0 && n < N_NODES) {
                g_asrc[n * 4 + hg] = ps;
                g_adst[n * 4 + hg] = pd;
            }
        }
        __syncthreads();
    }
}

__device__ __forceinline__ void load_W_As(char* smem, const __half* Wh,
                                          const float* as_, const float* ad_) {
    __half* Ws = (__half*)(smem + SM_WS);
    float* sAs = (float*)(smem + SM_AS);
    float* sAd = (float*)(smem + SM_AD);
    int tid = threadIdx.x;
    for (int i = tid; i < 2048; i += 256)
        *(uint4*)&Ws[i * 8] = *(const uint4*)&Wh[i * 8];
    if (tid < 256) {
        sAs[tid] = as_[tid];
        sAd[tid] = ad_[tid];
    }
}

// layers 2,3: X from global fp32
__global__ void __launch_bounds__(256) k_gemm_tc(
    const float* __restrict__ hin, const __half* __restrict__ Wh,
    const float* __restrict__ as_, const float* __restrict__ ad_)
{
    extern __shared__ char smem[];
    __half* Xs = (__half*)(smem + SM_XS);
    int row0 = blockIdx.x * 64;
    int tid = threadIdx.x;
    load_W_As(smem, Wh, as_, ad_);
    for (int i = tid; i < 1024; i += 256) {
        int row = i >> 4, k4 = (i & 15) * 4;
        float4 v = make_float4(0.f, 0.f, 0.f, 0.f);
        if (row0 + row < N_NODES) v = *(const float4*)&hin[(row0 + row) * 64 + k4];
        __half2 h0 = __floats2half2_rn(v.x, v.y);
        __half2 h1 = __floats2half2_rn(v.z, v.w);
        uint2 st;
        st.x = *(unsigned*)&h0;
        st.y = *(unsigned*)&h1;
        *(uint2*)&Xs[row * 64 + k4] = st;
    }
    __syncthreads();
    gemm_tc_core(smem, row0);
}

// layer 1: fused encoder MLP 8->32(elu)->64(elu) -> Xs + hA
__global__ void __launch_bounds__(256) k_gemm_tc_enc(
    const float* __restrict__ x,
    const float* __restrict__ We1, const float* __restrict__ be1,
    const float* __restrict__ We2, const float* __restrict__ be2,
    const __half* __restrict__ Wh,
    const float* __restrict__ as_, const float* __restrict__ ad_,
    float* __restrict__ hA)
{
    extern __shared__ char smem[];
    __half* Xs = (__half*)(smem + SM_XS);
    float* sE1 = (float*)(smem + SM_E1);
    float* sB1 = (float*)(smem + SM_B1);
    float* sE2 = (float*)(smem + SM_E2);
    float* sB2 = (float*)(smem + SM_B2);
    int row0 = blockIdx.x * 64;
    int tid = threadIdx.x;
    load_W_As(smem, Wh, as_, ad_);
    if (tid < 256) sE1[tid] = We1[tid];
    if (tid < 32) sB1[tid] = be1[tid];
    for (int i = tid; i < 2048; i += 256) sE2[i] = We2[i];
    if (tid < 64) sB2[tid] = be2[tid];
    __syncthreads();
    {
        int rr = tid >> 2;
        int q = tid & 3;
        int n = row0 + rr;
        float outv[16];
        if (n < N_NODES) {
            float4 xa = *(const float4*)&x[n * 8];
            float4 xb = *(const float4*)&x[n * 8 + 4];
            float xi[8] = {xa.x, xa.y, xa.z, xa.w, xb.x, xb.y, xb.z, xb.w};
            float hid[32];
#pragma unroll
            for (int j = 0; j < 32; j++) {
                float a = sB1[j];
#pragma unroll
                for (int i = 0; i < 8; i++) a += xi[i] * sE1[i * 32 + j];
                hid[j] = eluf(a);
            }
#pragma unroll
            for (int j = 0; j < 16; j++) {
                int jj = q * 16 + j;
                float a = sB2[jj];
#pragma unroll
                for (int i = 0; i < 32; i++) a += hid[i] * sE2[i * 64 + jj];
                outv[j] = eluf(a);
            }
#pragma unroll
            for (int j = 0; j < 16; j += 4)
                *(float4*)&hA[n * 64 + q * 16 + j] =
                    make_float4(outv[j], outv[j + 1], outv[j + 2], outv[j + 3]);
        } else {
#pragma unroll
            for (int j = 0; j < 16; j++) outv[j] = 0.f;
        }
#pragma unroll
        for (int j = 0; j < 16; j += 2) {
            __half2 h = __floats2half2_rn(outv[j], outv[j + 1]);
            *(__half2*)&Xs[rr * 64 + q * 16 + j] = h;
        }
    }
    __syncthreads();
    gemm_tc_core(smem, row0);
}

// ---------------- aggregation (single pass, shift-free softmax) ----------------
__device__ __forceinline__ void agg_node(
    int d, const float* __restrict__ bias, const float* __restrict__ hin,
    int* ss, float* se, float* dst64, int lane)
{
    int start = g_off[d], end = g_off[d + 1];
    float4 adst = *(const float4*)(g_adst + d * 4);
    int head = lane >> 3;
    unsigned long long acc2[4] = {0ull, 0ull, 0ull, 0ull};
    float den0 = 0.f, den1 = 0.f, den2 = 0.f, den3 = 0.f;
    const uint4* hp4 = (const uint4*)g_hproj;

    for (int base = start; base < end; base += 32) {
        int i = base + lane;
        int cnt = min(32, end - base);
        if (i < end) {
            int s = g_srcs[i];
            float4 a = *(const float4*)(g_asrc + s * 4);
            float e0 = __expf(lrelu(a.x + adst.x));
            float e1 = __expf(lrelu(a.y + adst.y));
            float e2 = __expf(lrelu(a.z + adst.z));
            float e3 = __expf(lrelu(a.w + adst.w));
            den0 += e0; den1 += e1; den2 += e2; den3 += e3;
            ss[lane] = s;
            se[lane * 4 + 0] = e0;
            se[lane * 4 + 1] = e1;
            se[lane * 4 + 2] = e2;
            se[lane * 4 + 3] = e3;
        }
        __syncwarp();
#pragma unroll 2
        for (int k = 0; k < cnt; k++) {
            int s = ss[k];
            float eh = se[k * 4 + head];
            unsigned long long ep = pack2(eh, eh);
            uint4 raw = __ldg(&hp4[(long long)s * 32 + lane]);
            float2 q0 = __half22float2(*(__half2*)&raw.x);
            float2 q1 = __half22float2(*(__half2*)&raw.y);
            float2 q2 = __half22float2(*(__half2*)&raw.z);
            float2 q3 = __half22float2(*(__half2*)&raw.w);
            fma2(acc2[0], ep, pack2(q0.x, q0.y));
            fma2(acc2[1], ep, pack2(q1.x, q1.y));
            fma2(acc2[2], ep, pack2(q2.x, q2.y));
            fma2(acc2[3], ep, pack2(q3.x, q3.y));
        }
        __syncwarp();
    }

#pragma unroll
    for (int o = 16; o; o >>= 1) {
        den0 += __shfl_xor_sync(0xffffffffu, den0, o);
        den1 += __shfl_xor_sync(0xffffffffu, den1, o);
        den2 += __shfl_xor_sync(0xffffffffu, den2, o);
        den3 += __shfl_xor_sync(0xffffffffu, den3, o);
    }
    float dh = (head == 0) ? den0 : (head == 1) ? den1 : (head == 2) ? den2 : den3;
    float inv = 1.f / (dh + 1e-16f);
    float acc[8];
#pragma unroll
    for (int j = 0; j < 4; j++) {
        float2 f = unpk2(acc2[j]);
        acc[2 * j] = f.x * inv;
        acc[2 * j + 1] = f.y * inv;
    }
#pragma unroll
    for (int j = 0; j < 8; j++) {
        acc[j] += __shfl_xor_sync(0xffffffffu, acc[j], 8);
        acc[j] += __shfl_xor_sync(0xffffffffu, acc[j], 16);
    }
    if (lane < 8) {
#pragma unroll
        for (int j = 0; j < 8; j++) {
            int cc = lane * 8 + j;
            dst64[cc] = 0.25f * acc[j] + bias[cc] + hin[d * 64 + cc];
        }
    }
}

__global__ void k_agg(const float* __restrict__ bias,
                      const float* __restrict__ hin, float* __restrict__ hout) {
    __shared__ int   s_src[8][32];
    __shared__ float s_e[8][128];
    int wib = threadIdx.x >> 5;
    int lane = threadIdx.x & 31;
    int d = blockIdx.x * 8 + wib;
    if (d >= N_NODES) return;
    agg_node(d, bias, hin, s_src[wib], s_e[wib], &hout[d * 64], lane);
}

__global__ void __launch_bounds__(256) k_agg_mlp(
    const float* __restrict__ bias, const float* __restrict__ hin,
    const float* __restrict__ Wo1, const float* __restrict__ bo1,
    const float* __restrict__ Wo2, const float* __restrict__ bo2,
    const float* __restrict__ Wo3, const float* __restrict__ bo3,
    float* __restrict__ out, int G)
{
    __shared__ float sW1[64 * 64], sW2[64 * 32], sW3[32 * 8];
    __shared__ float sb1[64], sb2[32], sb3[8];
    __shared__ int   s_src[8][32];
    __shared__ float s_e[8][128];
    __shared__ float mh[8][64], mh1[8][64], mh2[8][32];
    for (int i = threadIdx.x; i < 4096; i += 256) sW1[i] = Wo1[i];
    for (int i = threadIdx.x; i < 2048; i += 256) sW2[i] = Wo2[i];
    if (threadIdx.x < 256) sW3[threadIdx.x] = Wo3[threadIdx.x];
    if (threadIdx.x < 64) sb1[threadIdx.x] = bo1[threadIdx.x];
    if (threadIdx.x < 32) sb2[threadIdx.x] = bo2[threadIdx.x];
    if (threadIdx.x < 8) sb3[threadIdx.x] = bo3[threadIdx.x];
    __syncthreads();
    int wib = threadIdx.x >> 5;
    int lane = threadIdx.x & 31;
    int nw = G * 8;
    for (int d = blockIdx.x * 8 + wib; d < N_NODES; d += nw) {
        agg_node(d, bias, hin, s_src[wib], s_e[wib], mh[wib], lane);
        __syncwarp();
        float a0 = sb1[lane], a1 = sb1[lane + 32];
#pragma unroll
        for (int i = 0; i < 64; i++) {
            float xv = mh[wib][i];
            a0 += xv * sW1[i * 64 + lane];
            a1 += xv * sW1[i * 64 + lane + 32];
        }
        mh1[wib][lane] = eluf(a0);
        mh1[wib][lane + 32] = eluf(a1);
        __syncwarp();
        float a = sb2[lane];
#pragma unroll
        for (int i = 0; i < 64; i++) a += mh1[wib][i] * sW2[i * 32 + lane];
        mh2[wib][lane] = eluf(a);
        __syncwarp();
        if (lane < 8) {
            float o = sb3[lane];
#pragma unroll
            for (int i = 0; i < 32; i++) o += mh2[wib][i] * sW3[i * 8 + lane];
            out[d * 8 + lane] = o;
        }
        __syncwarp();
    }
}

// ---------------- launch ----------------
extern "C" void kernel_launch(void* const* d_in, const int* in_sizes, int n_in,
                              void* d_out, int out_size) {
    const float* x      = (const float*)d_in[0];
    const void*  ei     = d_in[1];
    const float* W_enc1 = (const float*)d_in[2];
    const float* b_enc1 = (const float*)d_in[3];
    const float* W_enc2 = (const float*)d_in[4];
    const float* b_enc2 = (const float*)d_in[5];
    const float* W_g[3] = {(const float*)d_in[6],  (const float*)d_in[10], (const float*)d_in[14]};
    const float* as_[3] = {(const float*)d_in[7],  (const float*)d_in[11], (const float*)d_in[15]};
    const float* ad_[3] = {(const float*)d_in[8],  (const float*)d_in[12], (const float*)d_in[16]};
    const float* bg_[3] = {(const float*)d_in[9],  (const float*)d_in[13], (const float*)d_in[17]};
    const float* W_o1 = (const float*)d_in[18];
    const float* b_o1 = (const float*)d_in[19];
    const float* W_o2 = (const float*)d_in[20];
    const float* b_o2 = (const float*)d_in[21];
    const float* W_o3 = (const float*)d_in[22];
    const float* b_o3 = (const float*)d_in[23];
    float* out = (float*)d_out;

    static bool inited = false;
    static cudaStream_t sB;
    static cudaEvent_t evF, evJ;
    static float* hA_p = nullptr;
    static float* hB_p = nullptr;
    static int* deg_p = nullptr;
    static __half* Wh_p = nullptr;
    if (!inited) {
        cudaStreamCreateWithFlags(&sB, cudaStreamNonBlocking);
        cudaEventCreateWithFlags(&evF, cudaEventDisableTiming);
        cudaEventCreateWithFlags(&evJ, cudaEventDisableTiming);
        cudaGetSymbolAddress((void**)&hA_p, g_hA);
        cudaGetSymbolAddress((void**)&hB_p, g_hB);
        cudaGetSymbolAddress((void**)&deg_p, g_deg);
        cudaGetSymbolAddress((void**)&Wh_p, g_Wh);
        cudaFuncSetAttribute(k_gemm_tc, cudaFuncAttributeMaxDynamicSharedMemorySize, SMEM_ATT);
        cudaFuncSetAttribute(k_gemm_tc_enc, cudaFuncAttributeMaxDynamicSharedMemorySize, SMEM_ENC);
        inited = true;
    }
    cudaStream_t s0 = 0;

    // fork
    cudaEventRecord(evF, s0);
    cudaStreamWaitEvent(sB, evF, 0);

    // stream 0: CSR build
    cudaMemsetAsync(deg_p, 0, (N_NODES + 160) * sizeof(int), s0);
    k_count<<<(N_EDGES + 255) / 256, 256, 0, s0>>>(ei);
    k_scan<<<NB_SCAN, 256, 0, s0>>>();
    k_scatter<<<(TOT_EDGES + 255) / 256, 256, 0, s0>>>(ei);

    // side stream: W fp16 conversion + fused encoder + layer-1 TC GEMM + att
    k_wconv<<<64, 256, 0, sB>>>(W_g[0], W_g[1], W_g[2]);
    k_gemm_tc_enc<<<NB_GEMM, 256, SMEM_ENC, sB>>>(x, W_enc1, b_enc1, W_enc2, b_enc2,
                                                  Wh_p, as_[0], ad_[0], hA_p);

    // join
    cudaEventRecord(evJ, sB);
    cudaStreamWaitEvent(s0, evJ, 0);

    k_agg<<<(N_NODES + 7) / 8, 256, 0, s0>>>(bg_[0], hA_p, hB_p);

    k_gemm_tc<<<NB_GEMM, 256, SMEM_ATT, s0>>>(hB_p, Wh_p + 16384, as_[1], ad_[1]);
    k_agg<<<(N_NODES + 7) / 8, 256, 0, s0>>>(bg_[1], hB_p, hA_p);

    k_gemm_tc<<<NB_GEMM, 256, SMEM_ATT, s0>>>(hA_p, Wh_p + 32768, as_[2], ad_[2]);
    const int GAGG = 625;
    k_agg_mlp<<<GAGG, 256, 0, s0>>>(bg_[2], hA_p, W_o1, b_o1, W_o2, b_o2,
                                    W_o3, b_o3, out, GAGG);

    (void)in_sizes; (void)n_in; (void)out_size;
}